// round 10
// baseline (speedup 1.0000x reference)
#include <cuda_runtime.h>
#include <cstring>

#define B_N 65536
#define D_N 1024
#define TILES 2048          // B_N / 32 rows per tile
#define NBLOCKS 152         // GB300: 152 SMs, 1 CTA/SM (smem-limited)
#define NTHREADS 512

// ---------------- device scratch (no runtime allocation allowed) ----------------
__device__ float2 g_Wp[16 * 1024];   // folded, swizzled W_eff: [pair p][s], cols (2p,2p+1)
__device__ float  g_zw[32];          // m_z[g] * W_zg[h]  at [g*8+h]

struct MainParams {
    const float* x;
    const float* hp;
    const float* cp;
    const float* zp;
    const float* Wh0; const float* Wh1; const float* Wh2; const float* Wh3;
    const float* b0;  const float* b1;  const float* b2;  const float* b3;
    const float* Wd1; const float* bd1;
    const float* Wd2; const float* bd2;
    const float* Wd3; const float* bd3;
    const float* m1;  const float* m2;
    float* out;
};

struct Smem {
    float2 Wp[16][1024];    // 128 KB  folded input weights (swizzled over d)
    float  gate[4][8][32];  // [rowgroup][row][j = g*8+h] pre-activations (x-part)
    float  ht[32][8];
    float  wh[4][64];       // [g][k*8+h]
    float  zw[32];
    float  bias[32];
};

// ---------------- packed f32x2 helpers ----------------
__device__ __forceinline__ unsigned long long pk2(float v) {
    unsigned long long r;
    asm("mov.b64 %0, {%1, %2};" : "=l"(r) : "f"(v), "f"(v));
    return r;
}
__device__ __forceinline__ void fma2(unsigned long long& d, unsigned long long a, unsigned long long b) {
    asm("fma.rn.f32x2 %0, %1, %2, %0;" : "+l"(d) : "l"(a), "l"(b));
}
__device__ __forceinline__ void unpk(unsigned long long v, float& lo, float& hi) {
    asm("mov.b64 {%0, %1}, %2;" : "=f"(lo), "=f"(hi) : "l"(v));
}
__device__ __forceinline__ float hsig(float x) {
    return fminf(fmaxf(fmaf(x, 0.16666667f, 0.5f), 0.0f), 1.0f);
}

// One halving step of the cross-lane transpose-reduce.
// v[0..2*N2) are packed f32x2 partials; after the step v[0..N2) hold the
// merged partials for the logical indices whose bit S equals (lane & S).
template<int S, int N2>
__device__ __forceinline__ void rstep(unsigned long long* v, int lane) {
#pragma unroll
    for (int j = 0; j < N2; j++) {
        unsigned long long a = v[j], b = v[j + N2];
        bool hi = (lane & S) != 0;
        unsigned long long mine  = hi ? b : a;
        unsigned long long yours = hi ? a : b;
        unsigned long long recv  = __shfl_xor_sync(0xffffffffu, yours, S);
        asm("add.rn.f32x2 %0, %1, %2;" : "=l"(v[j]) : "l"(mine), "l"(recv));
    }
}

// ---------------- prep: fold dropout mask into weights, swizzle over d ----------------
// main kernel reads d = c2*64 + lane*2 + dd  at smem index s = dd*512 + c2*32 + lane
__global__ void prep_kernel(const float* Wxi, const float* Wxf, const float* Wxc, const float* Wxo,
                            const float* mx,
                            const float* Wzi, const float* Wzf, const float* Wzc, const float* Wzo,
                            const float* mz) {
    int idx = blockIdx.x * 256 + threadIdx.x;     // 0 .. 32767 : (d, j)
    int d = idx >> 5;
    int j = idx & 31;
    int g = j >> 3;
    int h = j & 7;
    const float* Wx = (g == 0) ? Wxi : (g == 1) ? Wxf : (g == 2) ? Wxc : Wxo;
    float val = Wx[d * 8 + h] * mx[g * D_N + d];
    int p = j >> 1;
    int s = ((d & 1) << 9) | ((d >> 6) << 5) | ((d >> 1) & 31);
    reinterpret_cast<float*>(g_Wp)[((p << 10) + s) * 2 + (j & 1)] = val;

    if (idx < 32) {
        int gg = idx >> 3; int hh = idx & 7;
        const float* Wz = (gg == 0) ? Wzi : (gg == 1) ? Wzf : (gg == 2) ? Wzc : Wzo;
        g_zw[idx] = mz[gg] * Wz[hh];
    }
}

// ---------------- main fused kernel ----------------
__global__ __launch_bounds__(NTHREADS, 1)
void lstm_main(MainParams P) {
    extern __shared__ char raw[];
    Smem& S = *reinterpret_cast<Smem*>(raw);
    int t = threadIdx.x;

    // Fill smem W (once per CTA; persistent grid -> once per SM)
    {
        const float4* src = reinterpret_cast<const float4*>(g_Wp);
        float4* dst = reinterpret_cast<float4*>(S.Wp);
        #pragma unroll
        for (int i = 0; i < 16; i++)              // 8192 float4 / 512 threads
            dst[t + i * NTHREADS] = src[t + i * NTHREADS];
    }
    if (t < 256) {
        int g = t >> 6, rem = t & 63;
        const float* W = (g == 0) ? P.Wh0 : (g == 1) ? P.Wh1 : (g == 2) ? P.Wh2 : P.Wh3;
        S.wh[g][rem] = W[rem];
    }
    if (t < 32) {
        S.zw[t] = g_zw[t];
        int g = t >> 3; int h = t & 7;
        const float* b = (g == 0) ? P.b0 : (g == 1) ? P.b1 : (g == 2) ? P.b2 : P.b3;
        S.bias[t] = b[h];
    }
    __syncthreads();

    int w = t >> 5, lane = t & 31;
    int gp = w & 3;          // col group: pairs gp*4 .. gp*4+3  (cols gp*8 .. gp*8+7)
    int rg = w >> 2;         // row group 0..3 (8 rows each)

    for (int tile = blockIdx.x; tile < TILES; tile += gridDim.x) {
        int base_row = tile * 32;
        int row0 = base_row + rg * 8;

        unsigned long long acc[32];               // [r*4+p] packed f32x2
        #pragma unroll
        for (int a = 0; a < 32; a++) acc[a] = 0ull;

        const float* xbase = P.x + (size_t)row0 * D_N + lane * 2;
        for (int c2 = 0; c2 < 16; c2++) {
            float2 xv[8];
            #pragma unroll
            for (int r = 0; r < 8; r++)
                xv[r] = *reinterpret_cast<const float2*>(xbase + (size_t)r * D_N + c2 * 64);
            #pragma unroll
            for (int dd = 0; dd < 2; dd++) {
                int s = dd * 512 + c2 * 32 + lane;    // conflict-free (lane stride 1)
                unsigned long long wv[4];
                #pragma unroll
                for (int p = 0; p < 4; p++)
                    wv[p] = *reinterpret_cast<const unsigned long long*>(&S.Wp[gp * 4 + p][s]);
                #pragma unroll
                for (int r = 0; r < 8; r++) {
                    float xs = dd ? xv[r].y : xv[r].x;
                    unsigned long long a = pk2(xs);
                    #pragma unroll
                    for (int p = 0; p < 4; p++)
                        fma2(acc[r * 4 + p], a, wv[p]);   // 2 FMAs/inst
                }
            }
        }

        // transpose-reduce across lanes: after 5 steps lane l holds the full
        // sum for accumulator index a = l  (r = l>>2, p = l&3)
        rstep<16, 16>(acc, lane);
        rstep< 8,  8>(acc, lane);
        rstep< 4,  4>(acc, lane);
        rstep< 2,  2>(acc, lane);
        rstep< 1,  1>(acc, lane);
        {
            int r = lane >> 2, p = lane & 3;
            float lo, hi;
            unpk(acc[0], lo, hi);
            float2 v2; v2.x = lo; v2.y = hi;
            *reinterpret_cast<float2*>(&S.gate[rg][r][gp * 8 + 2 * p]) = v2;
        }
        __syncthreads();

        // gate epilogue: one thread per (row, h)  (first 256 threads)
        if (t < 256) {
            int rr = t >> 3, h = t & 7;
            int erg = rr >> 3, er = rr & 7;
            int row = base_row + rr;
            float hv[8];
            *reinterpret_cast<float4*>(hv)     = *reinterpret_cast<const float4*>(P.hp + (size_t)row * 8);
            *reinterpret_cast<float4*>(hv + 4) = *reinterpret_cast<const float4*>(P.hp + (size_t)row * 8 + 4);
            float zv = P.zp[row];
            float pre[4];
            #pragma unroll
            for (int g = 0; g < 4; g++) {
                float s = S.gate[erg][er][g * 8 + h] + S.bias[g * 8 + h];
                s = fmaf(zv, S.zw[g * 8 + h], s);
                #pragma unroll
                for (int k = 0; k < 8; k++)
                    s = fmaf(hv[k], S.wh[g][k * 8 + h], s);
                pre[g] = s;
            }
            float It = hsig(pre[0]);
            float Ft = hsig(pre[1]);
            float ct = Ft * P.cp[(size_t)row * 8 + h] + It * tanhf(pre[2]);
            float ht = hsig(pre[3]) * tanhf(ct);
            P.out[(size_t)B_N + (size_t)row * 8 + h]     = ht;   // ht block
            P.out[(size_t)9 * B_N + (size_t)row * 8 + h] = ct;   // ct block
            S.ht[rr][h] = ht;
        }
        __syncthreads();

        // dense head + zt: one thread per row (32 rows)
        if (t < 32) {
            int row = base_row + t;
            float hv[8];
            #pragma unroll
            for (int k = 0; k < 8; k++) hv[k] = S.ht[t][k];
            float d1[5], d2[5];
            #pragma unroll
            for (int wj = 0; wj < 5; wj++) {
                float s = P.bd1[wj];
                #pragma unroll
                for (int k = 0; k < 8; k++) s = fmaf(hv[k], P.Wd1[k * 5 + wj], s);
                d1[wj] = fmaxf(s, 0.0f) * P.m1[wj];
            }
            #pragma unroll
            for (int wj = 0; wj < 5; wj++) {
                float s = P.bd2[wj];
                #pragma unroll
                for (int k = 0; k < 5; k++) s = fmaf(d1[k], P.Wd2[k * 5 + wj], s);
                d2[wj] = fmaxf(s, 0.0f) * P.m2[wj];
            }
            float s = P.bd3[0];
            #pragma unroll
            for (int k = 0; k < 5; k++) s = fmaf(d2[k], P.Wd3[k], s);
            P.out[row] = P.zp[row] + fmaxf(s, 0.0f);             // zt block
        }
        // no trailing sync needed: next tile's smem writes are ordered by the syncs above
    }
}

// ---------------- launch ----------------
extern "C" void kernel_launch(void* const* d_in, const int* in_sizes, int n_in,
                              void* d_out, int out_size) {
    (void)in_sizes; (void)n_in; (void)out_size;
    const float* x   = (const float*)d_in[0];
    const float* hp  = (const float*)d_in[1];
    const float* cp  = (const float*)d_in[2];
    const float* zp  = (const float*)d_in[3];
    const float* Wxi = (const float*)d_in[4];
    const float* Wxf = (const float*)d_in[5];
    const float* Wxc = (const float*)d_in[6];
    const float* Wxo = (const float*)d_in[7];
    const float* Whi = (const float*)d_in[8];
    const float* Whf = (const float*)d_in[9];
    const float* Whc = (const float*)d_in[10];
    const float* Who = (const float*)d_in[11];
    const float* Wzi = (const float*)d_in[12];
    const float* Wzf = (const float*)d_in[13];
    const float* Wzc = (const float*)d_in[14];
    const float* Wzo = (const float*)d_in[15];
    const float* b_i = (const float*)d_in[16];
    const float* b_f = (const float*)d_in[17];
    const float* b_c = (const float*)d_in[18];
    const float* b_o = (const float*)d_in[19];
    const float* Wd1 = (const float*)d_in[20];
    const float* bd1 = (const float*)d_in[21];
    const float* Wd2 = (const float*)d_in[22];
    const float* bd2 = (const float*)d_in[23];
    const float* Wd3 = (const float*)d_in[24];
    const float* bd3 = (const float*)d_in[25];
    const float* m_x = (const float*)d_in[26];
    const float* m_z = (const float*)d_in[27];
    const float* m_1 = (const float*)d_in[28];
    const float* m_2 = (const float*)d_in[29];
    float* out = (float*)d_out;

    prep_kernel<<<128, 256>>>(Wxi, Wxf, Wxc, Wxo, m_x, Wzi, Wzf, Wzc, Wzo, m_z);

    MainParams P;
    P.x = x; P.hp = hp; P.cp = cp; P.zp = zp;
    P.Wh0 = Whi; P.Wh1 = Whf; P.Wh2 = Whc; P.Wh3 = Who;
    P.b0 = b_i; P.b1 = b_f; P.b2 = b_c; P.b3 = b_o;
    P.Wd1 = Wd1; P.bd1 = bd1; P.Wd2 = Wd2; P.bd2 = bd2; P.Wd3 = Wd3; P.bd3 = bd3;
    P.m1 = m_1; P.m2 = m_2;
    P.out = out;

    cudaFuncSetAttribute((const void*)lstm_main,
                         cudaFuncAttributeMaxDynamicSharedMemorySize,
                         (int)sizeof(Smem));
    lstm_main<<<NBLOCKS, NTHREADS, sizeof(Smem)>>>(P);
}

// round 14
// speedup vs baseline: 1.1347x; 1.1347x over previous
#include <cuda_runtime.h>
#include <cstdint>
#include <cstring>

#define B_N 65536
#define D_N 1024
#define TILES 2048          // B_N / 32 rows per tile
#define NBLOCKS 152         // GB300: 152 SMs, 1 CTA/SM (smem-limited)
#define NTHREADS 512
#define NSTAGE 4            // x staging ring depth (8KB per stage)

// ---------------- device scratch (no runtime allocation allowed) ----------------
__device__ float2 g_Wp[16 * 1024];   // folded, swizzled W_eff: [pair p][s], cols (2p,2p+1)
__device__ float  g_zw[32];          // m_z[g] * W_zg[h]  at [g*8+h]

struct MainParams {
    const float* x;
    const float* hp;
    const float* cp;
    const float* zp;
    const float* Wh0; const float* Wh1; const float* Wh2; const float* Wh3;
    const float* b0;  const float* b1;  const float* b2;  const float* b3;
    const float* Wd1; const float* bd1;
    const float* Wd2; const float* bd2;
    const float* Wd3; const float* bd3;
    const float* m1;  const float* m2;
    float* out;
};

struct Smem {
    float2 Wp[16][1024];        // 128 KB folded input weights (swizzled over d)
    float  Sx[NSTAGE][32][64];  // 32 KB  staged x chunks (cp.async ring)
    float  gate[4][8][32];      // [rowgroup][row][j = g*8+h] x-part pre-activations
    float  wh[4][64];           // [g][k*8+h]
    float  zw[32];
    float  bias[32];
    float  dh[96];              // dense head params: Wd1[0..39] bd1[40..44] Wd2[45..69]
                                //                    bd2[70..74] Wd3[75..79] bd3[80] m1[81..85] m2[86..90]
};

// ---------------- packed f32x2 helpers ----------------
__device__ __forceinline__ unsigned long long pk2(float v) {
    unsigned long long r;
    asm("mov.b64 %0, {%1, %2};" : "=l"(r) : "f"(v), "f"(v));
    return r;
}
__device__ __forceinline__ void fma2(unsigned long long& d, unsigned long long a, unsigned long long b) {
    asm("fma.rn.f32x2 %0, %1, %2, %0;" : "+l"(d) : "l"(a), "l"(b));
}
__device__ __forceinline__ void unpk(unsigned long long v, float& lo, float& hi) {
    asm("mov.b64 {%0, %1}, %2;" : "=f"(lo), "=f"(hi) : "l"(v));
}
__device__ __forceinline__ float hsig(float x) {
    return fminf(fmaxf(fmaf(x, 0.16666667f, 0.5f), 0.0f), 1.0f);
}
__device__ __forceinline__ uint32_t smem_u32(const void* p) {
    uint32_t a;
    asm("{ .reg .u64 tmp; cvta.to.shared.u64 tmp, %1; cvt.u32.u64 %0, tmp; }" : "=r"(a) : "l"(p));
    return a;
}

// One halving step of the cross-lane transpose-reduce.
template<int S, int N2>
__device__ __forceinline__ void rstep(unsigned long long* v, int lane) {
#pragma unroll
    for (int j = 0; j < N2; j++) {
        unsigned long long a = v[j], b = v[j + N2];
        bool hi = (lane & S) != 0;
        unsigned long long mine  = hi ? b : a;
        unsigned long long yours = hi ? a : b;
        unsigned long long recv  = __shfl_xor_sync(0xffffffffu, yours, S);
        asm("add.rn.f32x2 %0, %1, %2;" : "=l"(v[j]) : "l"(mine), "l"(recv));
    }
}

// Issue one 8KB x-chunk copy (32 rows x 64 cols) into ring stage (ci % NSTAGE).
// Every thread copies 16B; guarded copy + unconditional commit keeps group
// counts uniform across all threads.
__device__ __forceinline__ void issue_chunk(const float* x, uint32_t sx_base, int ci, int t) {
    int tile = blockIdx.x + (ci >> 4) * NBLOCKS;
    if (tile < TILES) {
        int c2 = ci & 15;
        int stage = ci & (NSTAGE - 1);
        const float* src = x + (size_t)(tile * 32 + (t >> 4)) * D_N + c2 * 64 + (t & 15) * 4;
        uint32_t dst = sx_base + stage * (32 * 64 * 4) + t * 16;
        asm volatile("cp.async.cg.shared.global [%0], [%1], 16;" :: "r"(dst), "l"(src) : "memory");
    }
    asm volatile("cp.async.commit_group;" ::: "memory");
}

// ---------------- prep: fold dropout mask into weights, swizzle over d ----------------
// main kernel reads d = c2*64 + lane*2 + dd  at smem index s = dd*512 + c2*32 + lane
__global__ void prep_kernel(const float* Wxi, const float* Wxf, const float* Wxc, const float* Wxo,
                            const float* mx,
                            const float* Wzi, const float* Wzf, const float* Wzc, const float* Wzo,
                            const float* mz) {
    int idx = blockIdx.x * 256 + threadIdx.x;     // 0 .. 32767 : (d, j)
    int d = idx >> 5;
    int j = idx & 31;
    int g = j >> 3;
    int h = j & 7;
    const float* Wx = (g == 0) ? Wxi : (g == 1) ? Wxf : (g == 2) ? Wxc : Wxo;
    float val = Wx[d * 8 + h] * mx[g * D_N + d];
    int p = j >> 1;
    int s = ((d & 1) << 9) | ((d >> 6) << 5) | ((d >> 1) & 31);
    reinterpret_cast<float*>(g_Wp)[((p << 10) + s) * 2 + (j & 1)] = val;

    if (idx < 32) {
        int gg = idx >> 3; int hh = idx & 7;
        const float* Wz = (gg == 0) ? Wzi : (gg == 1) ? Wzf : (gg == 2) ? Wzc : Wzo;
        g_zw[idx] = mz[gg] * Wz[hh];
    }
}

// ---------------- main fused kernel ----------------
__global__ __launch_bounds__(NTHREADS, 1)
void lstm_main(MainParams P) {
    extern __shared__ char raw[];
    Smem& S = *reinterpret_cast<Smem*>(raw);
    int t = threadIdx.x;

    // Fill smem W (once per CTA; persistent grid -> once per SM)
    {
        const float4* src = reinterpret_cast<const float4*>(g_Wp);
        float4* dst = reinterpret_cast<float4*>(S.Wp);
        #pragma unroll
        for (int i = 0; i < 16; i++)              // 8192 float4 / 512 threads
            dst[t + i * NTHREADS] = src[t + i * NTHREADS];
    }
    if (t < 256) {
        int g = t >> 6, rem = t & 63;
        const float* W = (g == 0) ? P.Wh0 : (g == 1) ? P.Wh1 : (g == 2) ? P.Wh2 : P.Wh3;
        S.wh[g][rem] = W[rem];
    }
    if (t < 32) {
        S.zw[t] = g_zw[t];
        int g = t >> 3; int h = t & 7;
        const float* b = (g == 0) ? P.b0 : (g == 1) ? P.b1 : (g == 2) ? P.b2 : P.b3;
        S.bias[t] = b[h];
    }
    // dense-head params into smem (once)
    if (t >= 416 && t < 512) {
        int i = t - 416;
        float v = 0.0f;
        if (i < 40)       v = P.Wd1[i];
        else if (i < 45)  v = P.bd1[i - 40];
        else if (i < 70)  v = P.Wd2[i - 45];
        else if (i < 75)  v = P.bd2[i - 70];
        else if (i < 80)  v = P.Wd3[i - 75];
        else if (i == 80) v = P.bd3[0];
        else if (i < 86)  v = P.m1[i - 81];
        else if (i < 91)  v = P.m2[i - 86];
        S.dh[i] = v;
    }
    __syncthreads();

    uint32_t sx_base = smem_u32(&S.Sx[0][0][0]);

    int w = t >> 5, lane = t & 31;
    int gp = w & 3;          // col group: pairs gp*4 .. gp*4+3  (cols gp*8 .. gp*8+7)
    int rg = w >> 2;         // row group 0..3 (8 rows each)

    // pipeline prologue: 3 chunks in flight
    issue_chunk(P.x, sx_base, 0, t);
    issue_chunk(P.x, sx_base, 1, t);
    issue_chunk(P.x, sx_base, 2, t);

    int ci = 0;              // CTA-local linear chunk counter
    for (int tile = blockIdx.x; tile < TILES; tile += NBLOCKS) {
        int base_row = tile * 32;

        unsigned long long acc[32];               // [r*4+p] packed f32x2
        #pragma unroll
        for (int a = 0; a < 32; a++) acc[a] = 0ull;

        for (int c2 = 0; c2 < 16; c2++, ci++) {
            asm volatile("cp.async.wait_group 2;" ::: "memory");
            __syncthreads();
            issue_chunk(P.x, sx_base, ci + 3, t);     // overlaps with compute below

            int stage = ci & (NSTAGE - 1);
            float2 xv[8];
            #pragma unroll
            for (int r = 0; r < 8; r++)
                xv[r] = *reinterpret_cast<const float2*>(&S.Sx[stage][rg * 8 + r][lane * 2]);
            #pragma unroll
            for (int dd = 0; dd < 2; dd++) {
                int s = dd * 512 + c2 * 32 + lane;    // conflict-free (lane stride 1)
                unsigned long long wv[4];
                #pragma unroll
                for (int p = 0; p < 4; p++)
                    wv[p] = *reinterpret_cast<const unsigned long long*>(&S.Wp[gp * 4 + p][s]);
                #pragma unroll
                for (int r = 0; r < 8; r++) {
                    float xs = dd ? xv[r].y : xv[r].x;
                    unsigned long long a = pk2(xs);
                    #pragma unroll
                    for (int p = 0; p < 4; p++)
                        fma2(acc[r * 4 + p], a, wv[p]);   // 2 FMAs/inst
                }
            }
        }

        // transpose-reduce across lanes: lane l ends with full sum for a = l
        rstep<16, 16>(acc, lane);
        rstep< 8,  8>(acc, lane);
        rstep< 4,  4>(acc, lane);
        rstep< 2,  2>(acc, lane);
        rstep< 1,  1>(acc, lane);
        {
            int r = lane >> 2, p = lane & 3;
            float lo, hi;
            unpk(acc[0], lo, hi);
            float2 v2; v2.x = lo; v2.y = hi;
            *reinterpret_cast<float2*>(&S.gate[rg][r][gp * 8 + 2 * p]) = v2;
        }
        __syncthreads();

        // ---- epilogue: all 16 warps, 2 rows each (lanes 0..15 active) ----
        int rl = lane >> 3;                // row within warp (valid for lane<16)
        int h  = lane & 7;
        int rr = w * 2 + rl;               // 0..31
        int row = base_row + rr;
        float htv = 0.0f, zv = 0.0f;
        if (lane < 16) {
            int erg = rr >> 3, er = rr & 7;
            float hv[8];
            *reinterpret_cast<float4*>(hv)     = *reinterpret_cast<const float4*>(P.hp + (size_t)row * 8);
            *reinterpret_cast<float4*>(hv + 4) = *reinterpret_cast<const float4*>(P.hp + (size_t)row * 8 + 4);
            zv = P.zp[row];
            float pre[4];
            #pragma unroll
            for (int g = 0; g < 4; g++) {
                float s = S.gate[erg][er][g * 8 + h] + S.bias[g * 8 + h];
                s = fmaf(zv, S.zw[g * 8 + h], s);
                #pragma unroll
                for (int k = 0; k < 8; k++)
                    s = fmaf(hv[k], S.wh[g][k * 8 + h], s);
                pre[g] = s;
            }
            float It = hsig(pre[0]);
            float Ft = hsig(pre[1]);
            float ct = Ft * P.cp[(size_t)row * 8 + h] + It * tanhf(pre[2]);
            htv = hsig(pre[3]) * tanhf(ct);
            P.out[(size_t)B_N + (size_t)row * 8 + h]     = htv;  // ht block
            P.out[(size_t)9 * B_N + (size_t)row * 8 + h] = ct;   // ct block
        }
        // gather the row's 8 ht values to the group leader via shuffle
        float hv8[8];
        #pragma unroll
        for (int k = 0; k < 8; k++)
            hv8[k] = __shfl_sync(0xffffffffu, htv, (lane & 24) + k);
        if (lane < 16 && h == 0) {
            // dense head for this row (leader lanes 0 and 8)
            float d1[5], d2[5];
            #pragma unroll
            for (int wj = 0; wj < 5; wj++) {
                float s = S.dh[40 + wj];
                #pragma unroll
                for (int k = 0; k < 8; k++) s = fmaf(hv8[k], S.dh[k * 5 + wj], s);
                d1[wj] = fmaxf(s, 0.0f) * S.dh[81 + wj];
            }
            #pragma unroll
            for (int wj = 0; wj < 5; wj++) {
                float s = S.dh[70 + wj];
                #pragma unroll
                for (int k = 0; k < 5; k++) s = fmaf(d1[k], S.dh[45 + k * 5 + wj], s);
                d2[wj] = fmaxf(s, 0.0f) * S.dh[86 + wj];
            }
            float s = S.dh[80];
            #pragma unroll
            for (int k = 0; k < 5; k++) s = fmaf(d2[k], S.dh[75 + k], s);
            P.out[row] = zv + fmaxf(s, 0.0f);                    // zt block
        }
        // next tile's first smem writes are ordered by the per-chunk barrier
    }
}

// ---------------- launch ----------------
extern "C" void kernel_launch(void* const* d_in, const int* in_sizes, int n_in,
                              void* d_out, int out_size) {
    (void)in_sizes; (void)n_in; (void)out_size;
    const float* x   = (const float*)d_in[0];
    const float* hp  = (const float*)d_in[1];
    const float* cp  = (const float*)d_in[2];
    const float* zp  = (const float*)d_in[3];
    const float* Wxi = (const float*)d_in[4];
    const float* Wxf = (const float*)d_in[5];
    const float* Wxc = (const float*)d_in[6];
    const float* Wxo = (const float*)d_in[7];
    const float* Whi = (const float*)d_in[8];
    const float* Whf = (const float*)d_in[9];
    const float* Whc = (const float*)d_in[10];
    const float* Who = (const float*)d_in[11];
    const float* Wzi = (const float*)d_in[12];
    const float* Wzf = (const float*)d_in[13];
    const float* Wzc = (const float*)d_in[14];
    const float* Wzo = (const float*)d_in[15];
    const float* b_i = (const float*)d_in[16];
    const float* b_f = (const float*)d_in[17];
    const float* b_c = (const float*)d_in[18];
    const float* b_o = (const float*)d_in[19];
    const float* Wd1 = (const float*)d_in[20];
    const float* bd1 = (const float*)d_in[21];
    const float* Wd2 = (const float*)d_in[22];
    const float* bd2 = (const float*)d_in[23];
    const float* Wd3 = (const float*)d_in[24];
    const float* bd3 = (const float*)d_in[25];
    const float* m_x = (const float*)d_in[26];
    const float* m_z = (const float*)d_in[27];
    const float* m_1 = (const float*)d_in[28];
    const float* m_2 = (const float*)d_in[29];
    float* out = (float*)d_out;

    prep_kernel<<<128, 256>>>(Wxi, Wxf, Wxc, Wxo, m_x, Wzi, Wzf, Wzc, Wzo, m_z);

    MainParams P;
    P.x = x; P.hp = hp; P.cp = cp; P.zp = zp;
    P.Wh0 = Whi; P.Wh1 = Whf; P.Wh2 = Whc; P.Wh3 = Who;
    P.b0 = b_i; P.b1 = b_f; P.b2 = b_c; P.b3 = b_o;
    P.Wd1 = Wd1; P.bd1 = bd1; P.Wd2 = Wd2; P.bd2 = bd2; P.Wd3 = Wd3; P.bd3 = bd3;
    P.m1 = m_1; P.m2 = m_2;
    P.out = out;

    cudaFuncSetAttribute((const void*)lstm_main,
                         cudaFuncAttributeMaxDynamicSharedMemorySize,
                         (int)sizeof(Smem));
    lstm_main<<<NBLOCKS, NTHREADS, sizeof(Smem)>>>(P);
}